// round 3
// baseline (speedup 1.0000x reference)
#include <cuda_runtime.h>
#include <cstdint>
#include <cstddef>

// Problem constants (fixed by the reference).
#define B_ROWS 32768
#define NDIM   64
#define HDIM   256
#define OFFDIM 2016   // 64*63/2

// ---------------------------------------------------------------------------
// Device scratch (no cudaMalloc allowed; __device__ globals are the sanctioned
// path). off is 264 MB; h buffers 32 MB each; diag 8 MB.
// ---------------------------------------------------------------------------
__device__ float g_h1[(size_t)B_ROWS * HDIM];
__device__ float g_h2[(size_t)B_ROWS * HDIM];
__device__ float g_diag[(size_t)B_ROWS * NDIM];
__device__ float g_off[(size_t)B_ROWS * OFFDIM];

// ---------------------------------------------------------------------------
// Packed f32x2 helpers (sm_100+). FFMA2 does 2 independent fp32 FMAs per lane
// per instruction -> 2x the 3-reg FFMA rate on B300. Bit-exact vs 2x fmaf.
// ---------------------------------------------------------------------------
__device__ __forceinline__ unsigned long long ffma2(unsigned long long a,
                                                    unsigned long long b,
                                                    unsigned long long c) {
    unsigned long long d;
    asm("fma.rn.f32x2 %0, %1, %2, %3;" : "=l"(d) : "l"(a), "l"(b), "l"(c));
    return d;
}
__device__ __forceinline__ unsigned long long pack2(float v) {
    unsigned long long d;
    asm("mov.b64 %0, {%1, %1};" : "=l"(d) : "f"(v));
    return d;
}
__device__ __forceinline__ void unpack2(unsigned long long p, float& lo, float& hi) {
    asm("mov.b64 {%0, %1}, %2;" : "=f"(lo), "=f"(hi) : "l"(p));
}

enum { EPI_TANH = 0, EPI_BIAS = 1, EPI_DIAG = 2 };

// ---------------------------------------------------------------------------
// Tiled SGEMM: C[M,N] = epi(A[M,K] @ W[K,N] + bias)
//   BM=128, BK=16, TM=8; BN/TN templated (128/8 or 64/4). 256 threads.
//   Register-prefetched single-buffer smem pipeline; f32x2 accumulators.
// M is always a multiple of 128 and K a multiple of 16 here; only N needs
// guarding (N=2016 tail tile).
// ---------------------------------------------------------------------------
template <int BN, int TN, int EPI>
__global__ void __launch_bounds__(256)
gemm_kernel(const float* __restrict__ A, const float* __restrict__ W,
            const float* __restrict__ bias, float* __restrict__ C,
            int M, int N, int K,
            const float* __restrict__ xin, const float* __restrict__ dmin) {
    constexpr int BM = 128, BK = 16, TM = 8;
    constexpr int NTX = BN / TN;                 // 16
    constexpr int LA  = (BM * BK) / (256 * 4);   // 2
    constexpr int LB  = (BK * BN) / (256 * 4);   // 2 (BN=128) or 1 (BN=64)

    __shared__ float As[BK][BM];
    __shared__ float Bs[BK][BN];

    const int tid = threadIdx.x;
    const int tx  = tid % NTX;
    const int ty  = tid / NTX;
    const int m0  = blockIdx.y * BM;
    const int n0  = blockIdx.x * BN;

    float4 ra[LA], rb[LB];

    auto ld = [&](int kt) {
#pragma unroll
        for (int u = 0; u < LA; u++) {
            int idx = tid * 4 + u * 1024;
            int mr = idx / BK, kc = idx % BK;
            ra[u] = *reinterpret_cast<const float4*>(
                &A[(size_t)(m0 + mr) * K + kt + kc]);
        }
#pragma unroll
        for (int u = 0; u < LB; u++) {
            int idx = tid * 4 + u * 1024;
            int kr = idx / BN, nc = idx % BN;
            float4 v = make_float4(0.f, 0.f, 0.f, 0.f);
            if (n0 + nc < N)  // N%4==0 and nc%4==0 -> full float4 valid
                v = *reinterpret_cast<const float4*>(
                    &W[(size_t)(kt + kr) * N + n0 + nc]);
            rb[u] = v;
        }
    };
    auto st = [&]() {
#pragma unroll
        for (int u = 0; u < LA; u++) {
            int idx = tid * 4 + u * 1024;
            int mr = idx / BK, kc = idx % BK;
            As[kc + 0][mr] = ra[u].x;
            As[kc + 1][mr] = ra[u].y;
            As[kc + 2][mr] = ra[u].z;
            As[kc + 3][mr] = ra[u].w;
        }
#pragma unroll
        for (int u = 0; u < LB; u++) {
            int idx = tid * 4 + u * 1024;
            int kr = idx / BN, nc = idx % BN;
            *reinterpret_cast<float4*>(&Bs[kr][nc]) = rb[u];
        }
    };

    unsigned long long acc[TM][TN / 2];
#pragma unroll
    for (int i = 0; i < TM; i++)
#pragma unroll
        for (int jp = 0; jp < TN / 2; jp++) acc[i][jp] = 0ULL;

    const int nT = K / BK;
    ld(0);
    st();
    __syncthreads();
    for (int t = 0; t < nT; t++) {
        if (t + 1 < nT) ld((t + 1) * BK);
#pragma unroll
        for (int k = 0; k < BK; k++) {
            // A fragment: 8 floats, two LDS.128 (broadcast across tx group)
            float a[TM];
            *reinterpret_cast<float4*>(&a[0]) =
                *reinterpret_cast<const float4*>(&As[k][ty * TM]);
            *reinterpret_cast<float4*>(&a[4]) =
                *reinterpret_cast<const float4*>(&As[k][ty * TM + 4]);
            // B fragment: TN contiguous floats via explicit float4 (LDS.128),
            // reinterpreted as f32x2 pairs.
            union {
                float4 v4[TN / 4];
                unsigned long long u64[TN / 2];
            } bfrag;
#pragma unroll
            for (int q = 0; q < TN / 4; q++)
                bfrag.v4[q] = *reinterpret_cast<const float4*>(
                    &Bs[k][tx * TN + 4 * q]);
#pragma unroll
            for (int i = 0; i < TM; i++) {
                unsigned long long ad = pack2(a[i]);
#pragma unroll
                for (int jp = 0; jp < TN / 2; jp++)
                    acc[i][jp] = ffma2(ad, bfrag.u64[jp], acc[i][jp]);
            }
        }
        __syncthreads();
        if (t + 1 < nT) {
            st();
            __syncthreads();
        }
    }

    // Epilogue
#pragma unroll
    for (int i = 0; i < TM; i++) {
        const int m = m0 + ty * TM + i;
#pragma unroll
        for (int jp = 0; jp < TN / 2; jp++) {
            float lo, hi;
            unpack2(acc[i][jp], lo, hi);
            float vals[2] = {lo, hi};
            const int n = n0 + tx * TN + 2 * jp;
#pragma unroll
            for (int s = 0; s < 2; s++) {
                int nn = n + s;
                if (nn < N) {
                    float v = vals[s] + bias[nn];
                    if (EPI == EPI_TANH) {
                        v = tanhf(v);
                    } else if (EPI == EPI_DIAG) {
                        float d = fmaxf(v, 0.f) + dmin[nn];
                        v = d * xin[(size_t)m * NDIM + nn];
                    }
                    C[(size_t)m * N + nn] = v;
                }
            }
        }
    }
}

// ---------------------------------------------------------------------------
// Final: per batch row, build L implicitly from (off, diag) and compute
//   out = L (L^T x).   tril row-major: off[i*(i-1)/2 + j] = L[i][j], i>j.
// 4 rows per 256-thread block (64 lanes per row).
// ---------------------------------------------------------------------------
__global__ void __launch_bounds__(256)
final_kernel(const float* __restrict__ off, const float* __restrict__ diag,
             const float* __restrict__ x, float* __restrict__ out) {
    __shared__ float soff[4][OFFDIM];
    __shared__ float sx[4][NDIM];
    __shared__ float sd[4][NDIM];
    __shared__ float sv[4][NDIM];

    const int r    = threadIdx.x >> 6;
    const int lane = threadIdx.x & 63;
    const size_t row = (size_t)blockIdx.x * 4 + r;

    sx[r][lane] = x[row * NDIM + lane];
    sd[r][lane] = diag[row * NDIM + lane];
    const float* offr = off + row * OFFDIM;
    for (int i = lane; i < OFFDIM; i += 64) soff[r][i] = offr[i];
    __syncthreads();

    // v_j = diag_j x_j + sum_{i>j} L[i][j] x_i
    float v = sd[r][lane] * sx[r][lane];
    for (int i = lane + 1; i < NDIM; i++)
        v += soff[r][i * (i - 1) / 2 + lane] * sx[r][i];
    sv[r][lane] = v;
    __syncthreads();

    // out_i = diag_i v_i + sum_{j<i} L[i][j] v_j
    float o = sd[r][lane] * v;
    const int base = lane * (lane - 1) / 2;
    for (int j = 0; j < lane; j++) o += soff[r][base + j] * sv[r][j];
    out[row * NDIM + lane] = o;
}

// ---------------------------------------------------------------------------
// Launch. Inputs (metadata order):
// x, Wd1, bd1, Wd2, bd2, Wdo, bdo, Wo1, bo1, Wo2, bo2, Woo, boo, damp_min
// ---------------------------------------------------------------------------
extern "C" void kernel_launch(void* const* d_in, const int* in_sizes, int n_in,
                              void* d_out, int out_size) {
    const float* x    = (const float*)d_in[0];
    const float* Wd1  = (const float*)d_in[1];
    const float* bd1  = (const float*)d_in[2];
    const float* Wd2  = (const float*)d_in[3];
    const float* bd2  = (const float*)d_in[4];
    const float* Wdo  = (const float*)d_in[5];
    const float* bdo  = (const float*)d_in[6];
    const float* Wo1  = (const float*)d_in[7];
    const float* bo1  = (const float*)d_in[8];
    const float* Wo2  = (const float*)d_in[9];
    const float* bo2  = (const float*)d_in[10];
    const float* Woo  = (const float*)d_in[11];
    const float* boo  = (const float*)d_in[12];
    const float* dmin = (const float*)d_in[13];
    float* out = (float*)d_out;

    float *h1, *h2, *dg, *off;
    cudaGetSymbolAddress((void**)&h1,  g_h1);
    cudaGetSymbolAddress((void**)&h2,  g_h2);
    cudaGetSymbolAddress((void**)&dg,  g_diag);
    cudaGetSymbolAddress((void**)&off, g_off);

    const dim3 thr(256);
    const int MB = B_ROWS / 128;  // 256 row-tiles

    // diag branch
    gemm_kernel<128, 8, EPI_TANH><<<dim3(2, MB), thr>>>(
        x, Wd1, bd1, h1, B_ROWS, HDIM, NDIM, nullptr, nullptr);
    gemm_kernel<128, 8, EPI_TANH><<<dim3(2, MB), thr>>>(
        h1, Wd2, bd2, h2, B_ROWS, HDIM, HDIM, nullptr, nullptr);
    gemm_kernel<64, 4, EPI_DIAG><<<dim3(1, MB), thr>>>(
        h2, Wdo, bdo, dg, B_ROWS, NDIM, HDIM, x, dmin);

    // off-diag branch (reuse h1/h2 scratch)
    gemm_kernel<128, 8, EPI_TANH><<<dim3(2, MB), thr>>>(
        x, Wo1, bo1, h1, B_ROWS, HDIM, NDIM, nullptr, nullptr);
    gemm_kernel<128, 8, EPI_TANH><<<dim3(2, MB), thr>>>(
        h1, Wo2, bo2, h2, B_ROWS, HDIM, HDIM, nullptr, nullptr);
    gemm_kernel<128, 8, EPI_BIAS><<<dim3(16, MB), thr>>>(
        h2, Woo, boo, off, B_ROWS, OFFDIM, HDIM, nullptr, nullptr);

    // L (L^T x)
    final_kernel<<<B_ROWS / 4, 256>>>(off, dg, x, out);
}

// round 5
// speedup vs baseline: 1.0881x; 1.0881x over previous
#include <cuda_runtime.h>
#include <cstdint>
#include <cstddef>

// Problem constants (fixed by the reference).
#define B_ROWS 32768
#define NDIM   64
#define HDIM   256
#define OFFDIM 2016   // 64*63/2

// ---------------------------------------------------------------------------
// Device scratch (__device__ globals; no allocation APIs allowed).
// ---------------------------------------------------------------------------
__device__ float g_h1[(size_t)B_ROWS * HDIM];
__device__ float g_h2[(size_t)B_ROWS * HDIM];
__device__ float g_diag[(size_t)B_ROWS * NDIM];
__device__ float g_off[(size_t)B_ROWS * OFFDIM];

// Transposed + tf32-split weights: Wt[n][k] (K contiguous => coalesced loads)
#define WT_D1 0
#define WT_D2 16384
#define WT_DO 81920
#define WT_O1 98304
#define WT_O2 114688
#define WT_OO 180224
#define WT_TOT 696320
__device__ uint32_t g_wth[WT_TOT];
__device__ uint32_t g_wtl[WT_TOT];

// ---------------------------------------------------------------------------
// tf32 hi/lo split (3xtf32 emulation of fp32: hi*hi + lo*hi + hi*lo, ~1e-7)
// cvt.rna.tf32.f32 is sm_80+ baseline PTX.
// ---------------------------------------------------------------------------
__device__ __forceinline__ uint32_t f2tf32(float x) {
    uint32_t r;
    asm("cvt.rna.tf32.f32 %0, %1;" : "=r"(r) : "f"(x));
    return r;
}
__device__ __forceinline__ void split_tf32(float x, uint32_t& hi, uint32_t& lo) {
    hi = f2tf32(x);
    lo = f2tf32(x - __uint_as_float(hi));
}

// m16n8k8 tf32 MMA (sm_80+ baseline; runs on tensor pipe of sm_103).
// A row-major frag: a0=[g][tig] a1=[g+8][tig] a2=[g][tig+4] a3=[g+8][tig+4]
// B col-major frag: b0=[tig][g] b1=[tig+4][g]     (k x n = 8 x 8)
// D: d0=[g][2tig] d1=[g][2tig+1] d2=[g+8][2tig] d3=[g+8][2tig+1]
__device__ __forceinline__ void mma8(float* d, const uint32_t* a,
                                     const uint32_t* b) {
    asm volatile(
        "mma.sync.aligned.m16n8k8.row.col.f32.tf32.tf32.f32 "
        "{%0,%1,%2,%3}, {%4,%5,%6,%7}, {%8,%9}, {%0,%1,%2,%3};"
        : "+f"(d[0]), "+f"(d[1]), "+f"(d[2]), "+f"(d[3])
        : "r"(a[0]), "r"(a[1]), "r"(a[2]), "r"(a[3]), "r"(b[0]), "r"(b[1]));
}

enum { EPI_TANH = 0, EPI_BIAS = 1, EPI_DIAG = 2 };

// ---------------------------------------------------------------------------
// Weight prep: W[K,N] fp32 -> Wt_hi/Wt_lo[N,K] tf32
// ---------------------------------------------------------------------------
__global__ void prep_w(const float* __restrict__ W, uint32_t* __restrict__ th,
                       uint32_t* __restrict__ tl, int K, int N) {
    int idx = blockIdx.x * 256 + threadIdx.x;
    if (idx >= K * N) return;
    int k = idx / N, n = idx % N;
    uint32_t hi, lo;
    split_tf32(W[idx], hi, lo);
    th[n * K + k] = hi;
    tl[n * K + k] = lo;
}

// ---------------------------------------------------------------------------
// tf32 mma.sync GEMM: C[M,N] = epi(A[M,K] @ W[K,N] + bias), 3xtf32.
// BM=128, BN=128, BK=32. 256 threads = 8 warps as 2(M)x4(N) -> 64x32/warp.
// Double-buffered smem chunks; smem layout [k][m(+4)] / [k][n(+4)]:
// fragment LDS conflict-free. Epilogue stages through smem for coalesced
// float4 global stores.
//
// dyn smem: 2 bufs x (AH|AL|BH|BL each 32x132 u32 = 16896B) = 135168B.
// Epilogue stage [128][132] fp32 = 67584B reuses buf0.
// ---------------------------------------------------------------------------
#define LDP 132          // padded row length (128+4) -> conflict-free frags
#define BUF_BYTES 67584  // 4 * 32*132*4

template <int EPI>
__global__ void __launch_bounds__(256, 1)
gemm_mma(const float* __restrict__ A, const uint32_t* __restrict__ Bth,
         const uint32_t* __restrict__ Btl, const float* __restrict__ bias,
         float* __restrict__ C, int K, int N, int ldc,
         const float* __restrict__ xin, const float* __restrict__ dmin) {
    extern __shared__ char smem[];
    const int tid  = threadIdx.x;
    const int wid  = tid >> 5, lane = tid & 31;
    const int g    = lane >> 2, tig = lane & 3;
    const int warpM = (wid >> 2) * 64;
    const int warpN = (wid & 3) * 32;
    const int m0 = blockIdx.y * 128;
    const int n0 = blockIdx.x * 128;

    float d[4][4][4];
#pragma unroll
    for (int mt = 0; mt < 4; mt++)
#pragma unroll
        for (int nt = 0; nt < 4; nt++)
#pragma unroll
            for (int j = 0; j < 4; j++) d[mt][nt][j] = 0.f;

    const int nT = K >> 5;

    auto ld_chunk = [&](int t, int b) {
        uint32_t* AH = (uint32_t*)(smem + b * BUF_BYTES);
        uint32_t* AL = AH + 32 * LDP;
        uint32_t* BH = AL + 32 * LDP;
        uint32_t* BL = BH + 32 * LDP;
        // A chunk [128 x 32] fp32 -> split hi/lo -> [k][m]
#pragma unroll
        for (int i = 0; i < 4; i++) {
            int idx = tid + i * 256;
            int row = idx >> 3, kg = (idx & 7) * 4;
            float4 v = *reinterpret_cast<const float4*>(
                A + (size_t)(m0 + row) * K + t * 32 + kg);
            float vv[4] = {v.x, v.y, v.z, v.w};
#pragma unroll
            for (int j = 0; j < 4; j++) {
                uint32_t h, l;
                split_tf32(vv[j], h, l);
                AH[(kg + j) * LDP + row] = h;
                AL[(kg + j) * LDP + row] = l;
            }
        }
        // B chunk [128 x 32] pre-split tf32 -> [k][n]; zero-fill OOB n.
#pragma unroll
        for (int i = 0; i < 4; i++) {
            int idx = tid + i * 256;
            int row = idx >> 3, kg = (idx & 7) * 4;
            uint4 h = make_uint4(0u, 0u, 0u, 0u);
            uint4 l = make_uint4(0u, 0u, 0u, 0u);
            if (n0 + row < N) {
                h = *reinterpret_cast<const uint4*>(
                    Bth + (size_t)(n0 + row) * K + t * 32 + kg);
                l = *reinterpret_cast<const uint4*>(
                    Btl + (size_t)(n0 + row) * K + t * 32 + kg);
            }
            uint32_t hh[4] = {h.x, h.y, h.z, h.w};
            uint32_t ll[4] = {l.x, l.y, l.z, l.w};
#pragma unroll
            for (int j = 0; j < 4; j++) {
                BH[(kg + j) * LDP + row] = hh[j];
                BL[(kg + j) * LDP + row] = ll[j];
            }
        }
    };

    ld_chunk(0, 0);
    __syncthreads();
    for (int t = 0; t < nT; t++) {
        if (t + 1 < nT) ld_chunk(t + 1, (t + 1) & 1);

        const uint32_t* AH = (const uint32_t*)(smem + (t & 1) * BUF_BYTES);
        const uint32_t* AL = AH + 32 * LDP;
        const uint32_t* BH = AL + 32 * LDP;
        const uint32_t* BL = BH + 32 * LDP;
#pragma unroll
        for (int ks = 0; ks < 4; ks++) {
            const int k0 = ks * 8;
            const int r0 = (k0 + tig) * LDP, r1 = (k0 + tig + 4) * LDP;
            uint32_t ah[4][4], al[4][4];
#pragma unroll
            for (int mt = 0; mt < 4; mt++) {
                int m = warpM + mt * 16 + g;
                ah[mt][0] = AH[r0 + m];     ah[mt][1] = AH[r0 + m + 8];
                ah[mt][2] = AH[r1 + m];     ah[mt][3] = AH[r1 + m + 8];
                al[mt][0] = AL[r0 + m];     al[mt][1] = AL[r0 + m + 8];
                al[mt][2] = AL[r1 + m];     al[mt][3] = AL[r1 + m + 8];
            }
#pragma unroll
            for (int nt = 0; nt < 4; nt++) {
                int n = warpN + nt * 8 + g;
                uint32_t bh[2] = {BH[r0 + n], BH[r1 + n]};
                uint32_t bl[2] = {BL[r0 + n], BL[r1 + n]};
#pragma unroll
                for (int mt = 0; mt < 4; mt++) {
                    mma8(d[mt][nt], ah[mt], bh);  // hi*hi
                    mma8(d[mt][nt], al[mt], bh);  // lo*hi
                    mma8(d[mt][nt], ah[mt], bl);  // hi*lo
                }
            }
        }
        __syncthreads();
    }

    // Epilogue: stage D tile in smem (reuse buf0), then coalesced STG.
    float* stg = (float*)smem;  // [128][LDP]
#pragma unroll
    for (int mt = 0; mt < 4; mt++)
#pragma unroll
        for (int nt = 0; nt < 4; nt++) {
            int r = warpM + mt * 16 + g;
            int c = warpN + nt * 8 + tig * 2;
            stg[r * LDP + c]           = d[mt][nt][0];
            stg[r * LDP + c + 1]       = d[mt][nt][1];
            stg[(r + 8) * LDP + c]     = d[mt][nt][2];
            stg[(r + 8) * LDP + c + 1] = d[mt][nt][3];
        }
    __syncthreads();
    {
        const int r  = tid >> 1;
        const int cb = (tid & 1) * 64;
#pragma unroll
        for (int j = 0; j < 16; j++) {
            int c = cb + j * 4;
            if (n0 + c < N) {  // N,c multiples of 4 -> whole float4 valid
                const float* s = stg + r * LDP + c;
                float v[4] = {s[0], s[1], s[2], s[3]};
#pragma unroll
                for (int q = 0; q < 4; q++) {
                    float val = v[q] + bias[n0 + c + q];
                    if (EPI == EPI_TANH) {
                        val = tanhf(val);
                    } else if (EPI == EPI_DIAG) {
                        float dd = fmaxf(val, 0.f) + dmin[n0 + c + q];
                        val = dd * xin[(size_t)(m0 + r) * NDIM + n0 + c + q];
                    }
                    v[q] = val;
                }
                *reinterpret_cast<float4*>(C + (size_t)(m0 + r) * ldc + n0 + c) =
                    make_float4(v[0], v[1], v[2], v[3]);
            }
        }
    }
}

// ---------------------------------------------------------------------------
// Final: out = L (L^T x) per batch row; L from (off, diag).
// ---------------------------------------------------------------------------
__global__ void __launch_bounds__(256)
final_kernel(const float* __restrict__ off, const float* __restrict__ diag,
             const float* __restrict__ x, float* __restrict__ out) {
    __shared__ float soff[4][OFFDIM];
    __shared__ float sx[4][NDIM];
    __shared__ float sd[4][NDIM];
    __shared__ float sv[4][NDIM];

    const int r    = threadIdx.x >> 6;
    const int lane = threadIdx.x & 63;
    const size_t row = (size_t)blockIdx.x * 4 + r;

    sx[r][lane] = x[row * NDIM + lane];
    sd[r][lane] = diag[row * NDIM + lane];
    const float* offr = off + row * OFFDIM;
    for (int i = lane; i < OFFDIM; i += 64) soff[r][i] = offr[i];
    __syncthreads();

    float v = sd[r][lane] * sx[r][lane];
    for (int i = lane + 1; i < NDIM; i++)
        v += soff[r][i * (i - 1) / 2 + lane] * sx[r][i];
    sv[r][lane] = v;
    __syncthreads();

    float o = sd[r][lane] * v;
    const int base = lane * (lane - 1) / 2;
    for (int j = 0; j < lane; j++) o += soff[r][base + j] * sv[r][j];
    out[row * NDIM + lane] = o;
}

// ---------------------------------------------------------------------------
// Launch. Inputs: x, Wd1, bd1, Wd2, bd2, Wdo, bdo, Wo1, bo1, Wo2, bo2,
//                 Woo, boo, damp_min
// ---------------------------------------------------------------------------
#define GEMM_SMEM (2 * BUF_BYTES)  // 135168

extern "C" void kernel_launch(void* const* d_in, const int* in_sizes, int n_in,
                              void* d_out, int out_size) {
    const float* x    = (const float*)d_in[0];
    const float* Wd1  = (const float*)d_in[1];
    const float* bd1  = (const float*)d_in[2];
    const float* Wd2  = (const float*)d_in[3];
    const float* bd2  = (const float*)d_in[4];
    const float* Wdo  = (const float*)d_in[5];
    const float* bdo  = (const float*)d_in[6];
    const float* Wo1  = (const float*)d_in[7];
    const float* bo1  = (const float*)d_in[8];
    const float* Wo2  = (const float*)d_in[9];
    const float* bo2  = (const float*)d_in[10];
    const float* Woo  = (const float*)d_in[11];
    const float* boo  = (const float*)d_in[12];
    const float* dmin = (const float*)d_in[13];
    float* out = (float*)d_out;

    float *h1, *h2, *dg, *off;
    uint32_t *wth, *wtl;
    cudaGetSymbolAddress((void**)&h1,  g_h1);
    cudaGetSymbolAddress((void**)&h2,  g_h2);
    cudaGetSymbolAddress((void**)&dg,  g_diag);
    cudaGetSymbolAddress((void**)&off, g_off);
    cudaGetSymbolAddress((void**)&wth, g_wth);
    cudaGetSymbolAddress((void**)&wtl, g_wtl);

    cudaFuncSetAttribute(gemm_mma<EPI_TANH>,
                         cudaFuncAttributeMaxDynamicSharedMemorySize, GEMM_SMEM);
    cudaFuncSetAttribute(gemm_mma<EPI_BIAS>,
                         cudaFuncAttributeMaxDynamicSharedMemorySize, GEMM_SMEM);
    cudaFuncSetAttribute(gemm_mma<EPI_DIAG>,
                         cudaFuncAttributeMaxDynamicSharedMemorySize, GEMM_SMEM);

    // Weight prep (transpose + tf32 split); tiny.
    prep_w<<<(NDIM * HDIM + 255) / 256, 256>>>(Wd1, wth + WT_D1, wtl + WT_D1, NDIM, HDIM);
    prep_w<<<(HDIM * HDIM + 255) / 256, 256>>>(Wd2, wth + WT_D2, wtl + WT_D2, HDIM, HDIM);
    prep_w<<<(HDIM * NDIM + 255) / 256, 256>>>(Wdo, wth + WT_DO, wtl + WT_DO, HDIM, NDIM);
    prep_w<<<(NDIM * HDIM + 255) / 256, 256>>>(Wo1, wth + WT_O1, wtl + WT_O1, NDIM, HDIM);
    prep_w<<<(HDIM * HDIM + 255) / 256, 256>>>(Wo2, wth + WT_O2, wtl + WT_O2, HDIM, HDIM);
    prep_w<<<(HDIM * OFFDIM + 255) / 256, 256>>>(Woo, wth + WT_OO, wtl + WT_OO, HDIM, OFFDIM);

    const int MB = B_ROWS / 128;  // 256 m-tiles
    // diag branch
    gemm_mma<EPI_TANH><<<dim3(2, MB), 256, GEMM_SMEM>>>(
        x, wth + WT_D1, wtl + WT_D1, bd1, h1, NDIM, HDIM, HDIM, nullptr, nullptr);
    gemm_mma<EPI_TANH><<<dim3(2, MB), 256, GEMM_SMEM>>>(
        h1, wth + WT_D2, wtl + WT_D2, bd2, h2, HDIM, HDIM, HDIM, nullptr, nullptr);
    gemm_mma<EPI_DIAG><<<dim3(1, MB), 256, GEMM_SMEM>>>(
        h2, wth + WT_DO, wtl + WT_DO, bdo, dg, HDIM, NDIM, NDIM, x, dmin);
    // off branch
    gemm_mma<EPI_TANH><<<dim3(2, MB), 256, GEMM_SMEM>>>(
        x, wth + WT_O1, wtl + WT_O1, bo1, h1, NDIM, HDIM, HDIM, nullptr, nullptr);
    gemm_mma<EPI_TANH><<<dim3(2, MB), 256, GEMM_SMEM>>>(
        h1, wth + WT_O2, wtl + WT_O2, bo2, h2, HDIM, HDIM, HDIM, nullptr, nullptr);
    gemm_mma<EPI_BIAS><<<dim3(16, MB), 256, GEMM_SMEM>>>(
        h2, wth + WT_OO, wtl + WT_OO, boo, off, HDIM, OFFDIM, OFFDIM, nullptr, nullptr);

    final_kernel<<<B_ROWS / 4, 256>>>(off, dg, x, out);
}

// round 6
// speedup vs baseline: 1.5209x; 1.3977x over previous
#include <cuda_runtime.h>
#include <cstdint>
#include <cstddef>

// Problem constants (fixed by the reference).
#define B_ROWS 32768
#define NDIM   64
#define HDIM   256
#define OFFDIM 2016   // 64*63/2

// ---------------------------------------------------------------------------
// Device scratch (__device__ globals; no allocation APIs allowed).
// ---------------------------------------------------------------------------
__device__ float g_h1[(size_t)B_ROWS * HDIM];
__device__ float g_h2[(size_t)B_ROWS * HDIM];
__device__ float g_h3[(size_t)B_ROWS * HDIM];
__device__ float g_diag[(size_t)B_ROWS * NDIM];
__device__ float g_off[(size_t)B_ROWS * OFFDIM];

// Transposed + tf32-split weights: Wt[n][k] (K contiguous => coalesced loads)
#define WT_D1 0
#define WT_D2 16384
#define WT_DO 81920
#define WT_O1 98304
#define WT_O2 114688
#define WT_OO 180224
#define WT_TOT 696320
__device__ uint32_t g_wth[WT_TOT];
__device__ uint32_t g_wtl[WT_TOT];

// ---------------------------------------------------------------------------
// tf32 hi/lo split (3xtf32 emulation of fp32: hi*hi + lo*hi + hi*lo, ~eps^2)
// ---------------------------------------------------------------------------
__device__ __forceinline__ uint32_t f2tf32(float x) {
    uint32_t r;
    asm("cvt.rna.tf32.f32 %0, %1;" : "=r"(r) : "f"(x));
    return r;
}
__device__ __forceinline__ void split_tf32(float x, uint32_t& hi, uint32_t& lo) {
    hi = f2tf32(x);
    lo = f2tf32(x - __uint_as_float(hi));
}

// m16n8k8 tf32 MMA (sm_80+ baseline; tensor pipe).
// A frag: a0=[g][tig] a1=[g+8][tig] a2=[g][tig+4] a3=[g+8][tig+4]
// B frag: b0=[k=tig][n=g] b1=[k=tig+4][n=g]
// D:      d0=[g][2tig] d1=[g][2tig+1] d2=[g+8][2tig] d3=[g+8][2tig+1]
__device__ __forceinline__ void mma8(float* d, const uint32_t* a,
                                     const uint32_t* b) {
    asm volatile(
        "mma.sync.aligned.m16n8k8.row.col.f32.tf32.tf32.f32 "
        "{%0,%1,%2,%3}, {%4,%5,%6,%7}, {%8,%9}, {%0,%1,%2,%3};"
        : "+f"(d[0]), "+f"(d[1]), "+f"(d[2]), "+f"(d[3])
        : "r"(a[0]), "r"(a[1]), "r"(a[2]), "r"(a[3]), "r"(b[0]), "r"(b[1]));
}

// ldmatrix x4 on tf32 data: each 8x16B tile -> 1 u32/lane, lane 4r+c <- row r
// word c. With [row][k] 128B-row swizzled smem this yields mma fragments
// directly (A: tiles {m0-7,k0-3},{m8-15,k0-3},{m0-7,k4-7},{m8-15,k4-7}).
__device__ __forceinline__ void ldsm4(uint32_t* r, uint32_t addr) {
    asm volatile(
        "ldmatrix.sync.aligned.m8n8.x4.shared.b16 {%0,%1,%2,%3}, [%4];"
        : "=r"(r[0]), "=r"(r[1]), "=r"(r[2]), "=r"(r[3]) : "r"(addr));
}

__device__ __forceinline__ uint32_t smem_u32(const void* p) {
    uint32_t a;
    asm("{ .reg .u64 t; cvta.to.shared.u64 t, %1; cvt.u32.u64 %0, t; }"
        : "=r"(a) : "l"(p));
    return a;
}

enum { EPI_TANH = 0, EPI_BIAS = 1, EPI_DIAG = 2 };

// ---------------------------------------------------------------------------
// Single prep launch: all 6 weights, W[K,N] fp32 -> Wt_hi/Wt_lo[N,K] tf32.
// (One launch so ncu -s 5 -c 1 captures the Woo GEMM as launch #6.)
// ---------------------------------------------------------------------------
__global__ void prep_all(const float* __restrict__ Wd1, const float* __restrict__ Wd2,
                         const float* __restrict__ Wdo, const float* __restrict__ Wo1,
                         const float* __restrict__ Wo2, const float* __restrict__ Woo,
                         uint32_t* __restrict__ th, uint32_t* __restrict__ tl) {
    int idx = blockIdx.x * 256 + threadIdx.x;
    const float* W;
    int K, N, base, local;
    if (idx < 16384)       { W = Wd1; K = 64;  N = 256;  base = WT_D1; local = idx; }
    else if (idx < 81920)  { W = Wd2; K = 256; N = 256;  base = WT_D2; local = idx - 16384; }
    else if (idx < 98304)  { W = Wdo; K = 256; N = 64;   base = WT_DO; local = idx - 81920; }
    else if (idx < 114688) { W = Wo1; K = 64;  N = 256;  base = WT_O1; local = idx - 98304; }
    else if (idx < 180224) { W = Wo2; K = 256; N = 256;  base = WT_O2; local = idx - 114688; }
    else if (idx < 696320) { W = Woo; K = 256; N = 2016; base = WT_OO; local = idx - 180224; }
    else return;
    int k = local / N, n = local % N;
    uint32_t hi, lo;
    split_tf32(W[(size_t)k * N + n], hi, lo);
    th[(size_t)base + (size_t)n * K + k] = hi;
    tl[(size_t)base + (size_t)n * K + k] = lo;
}

// ---------------------------------------------------------------------------
// tf32 mma.sync GEMM, 3xtf32. BM=128, BN=128, BK=32; 8 warps (2Mx4N),
// warp tile 64x32. ldmatrix fragment loads from SW128-swizzled [row][k]
// smem; STS.128 conflict-free writes; LDG(t+1) issued before chunk-t MMAs,
// split+STS after them (latency hidden under tensor work).
//
// smem: 2 bufs x 64KB (AH|AL|BH|BL, 16KB each) = 128KB. Epilogue staging
// [128][132] fp32 (67.6KB) reuses the buffers.
// ---------------------------------------------------------------------------
#define BUFB 65536
#define SOFF_AL 16384
#define SOFF_BH 32768
#define SOFF_BL 49152
#define LDP 132
#define GEMM_SMEM (2 * BUFB)

template <int EPI>
__global__ void __launch_bounds__(256, 1)
gemm_mma(const float* __restrict__ A, const uint32_t* __restrict__ Bth,
         const uint32_t* __restrict__ Btl, const float* __restrict__ bias,
         float* __restrict__ C, int K, int N, int ldc,
         const float* __restrict__ xin, const float* __restrict__ dmin) {
    extern __shared__ char smem[];
    const uint32_t sbase = smem_u32(smem);
    const int tid = threadIdx.x;
    const int wid = tid >> 5, lane = tid & 31;
    const int g = lane >> 2, tig = lane & 3;
    const int warpM = (wid >> 2) * 64;
    const int warpN = (wid & 3) * 32;
    const int m0 = blockIdx.y * 128;
    const int n0 = blockIdx.x * 128;

    // ldmatrix lane constants. 16B-col swizzle: col' = col ^ (row & 7).
    const uint32_t xorv = lane & 7;
    const int aRow = (lane & 7) + ((lane >> 3) & 1) * 8;  // A: +8 rows for tiles 1,3
    const int aKq  = lane >> 4;                           // A: +1 col for tiles 2,3
    const int bRow = (lane & 7) + ((lane >> 4) & 1) * 8;  // B: +8 n for tiles 2,3
    const int bKq  = (lane >> 3) & 1;                     // B: +1 col for tiles 1,3

    float d[4][4][4];
#pragma unroll
    for (int mt = 0; mt < 4; mt++)
#pragma unroll
        for (int nt = 0; nt < 4; nt++)
#pragma unroll
            for (int j = 0; j < 4; j++) d[mt][nt][j] = 0.f;

    float4 sa[4];
    uint4 sbh[4], sbl[4];

    auto ldg_stage = [&](int t) {
        const float* Ab = A + (size_t)m0 * K + t * 32;
#pragma unroll
        for (int i = 0; i < 4; i++) {
            int idx = tid + i * 256, row = idx >> 3, kq = idx & 7;
            sa[i] = *reinterpret_cast<const float4*>(Ab + (size_t)row * K + kq * 4);
        }
#pragma unroll
        for (int i = 0; i < 4; i++) {
            int idx = tid + i * 256, row = idx >> 3, kq = idx & 7;
            if (n0 + row < N) {
                sbh[i] = *reinterpret_cast<const uint4*>(
                    Bth + (size_t)(n0 + row) * K + t * 32 + kq * 4);
                sbl[i] = *reinterpret_cast<const uint4*>(
                    Btl + (size_t)(n0 + row) * K + t * 32 + kq * 4);
            } else {
                sbh[i] = make_uint4(0u, 0u, 0u, 0u);
                sbl[i] = make_uint4(0u, 0u, 0u, 0u);
            }
        }
    };

    auto split_sts = [&](int b) {
        char* buf = smem + b * BUFB;
#pragma unroll
        for (int i = 0; i < 4; i++) {
            int idx = tid + i * 256, row = idx >> 3, kq = idx & 7;
            uint32_t off = (uint32_t)row * 128 + (((uint32_t)kq ^ (row & 7)) << 4);
            uint4 h, l;
            split_tf32(sa[i].x, h.x, l.x);
            split_tf32(sa[i].y, h.y, l.y);
            split_tf32(sa[i].z, h.z, l.z);
            split_tf32(sa[i].w, h.w, l.w);
            *reinterpret_cast<uint4*>(buf + off)           = h;
            *reinterpret_cast<uint4*>(buf + SOFF_AL + off) = l;
        }
#pragma unroll
        for (int i = 0; i < 4; i++) {
            int idx = tid + i * 256, row = idx >> 3, kq = idx & 7;
            uint32_t off = (uint32_t)row * 128 + (((uint32_t)kq ^ (row & 7)) << 4);
            *reinterpret_cast<uint4*>(buf + SOFF_BH + off) = sbh[i];
            *reinterpret_cast<uint4*>(buf + SOFF_BL + off) = sbl[i];
        }
    };

    auto mma_chunk = [&](int b) {
        const uint32_t AH = sbase + b * BUFB;
        const uint32_t AL = AH + SOFF_AL;
        const uint32_t BH = AH + SOFF_BH;
        const uint32_t BL = AH + SOFF_BL;
#pragma unroll
        for (int ks = 0; ks < 4; ks++) {
            const uint32_t acol = (((uint32_t)(ks * 2 + aKq)) ^ xorv) << 4;
            const uint32_t bcol = (((uint32_t)(ks * 2 + bKq)) ^ xorv) << 4;
            uint32_t ah[4][4], al[4][4];
#pragma unroll
            for (int mt = 0; mt < 4; mt++) {
                uint32_t ro = (uint32_t)(warpM + mt * 16 + aRow) * 128 + acol;
                ldsm4(ah[mt], AH + ro);
                ldsm4(al[mt], AL + ro);
            }
#pragma unroll
            for (int p = 0; p < 2; p++) {
                uint32_t bh[4], bl[4];
                uint32_t ro = (uint32_t)(warpN + p * 16 + bRow) * 128 + bcol;
                ldsm4(bh, BH + ro);
                ldsm4(bl, BL + ro);
#pragma unroll
                for (int q = 0; q < 2; q++) {
                    const int nt = p * 2 + q;
#pragma unroll
                    for (int mt = 0; mt < 4; mt++) {
                        mma8(d[mt][nt], ah[mt], bh + q * 2);  // hi*hi
                        mma8(d[mt][nt], al[mt], bh + q * 2);  // lo*hi
                        mma8(d[mt][nt], ah[mt], bl + q * 2);  // hi*lo
                    }
                }
            }
        }
    };

    const int nT = K >> 5;
    ldg_stage(0);
    split_sts(0);
    __syncthreads();
    for (int t = 0; t < nT; t++) {
        if (t + 1 < nT) ldg_stage(t + 1);   // LDG only; consumed after MMAs
        mma_chunk(t & 1);                   // tensor work hides LDG latency
        if (t + 1 < nT) split_sts((t + 1) & 1);
        __syncthreads();
    }

    // Epilogue: stage D in smem (reuse buffers), coalesced float4 STG.
    float* stg = reinterpret_cast<float*>(smem);  // [128][LDP]
#pragma unroll
    for (int mt = 0; mt < 4; mt++)
#pragma unroll
        for (int nt = 0; nt < 4; nt++) {
            int r = warpM + mt * 16 + g;
            int c = warpN + nt * 8 + tig * 2;
            stg[r * LDP + c]           = d[mt][nt][0];
            stg[r * LDP + c + 1]       = d[mt][nt][1];
            stg[(r + 8) * LDP + c]     = d[mt][nt][2];
            stg[(r + 8) * LDP + c + 1] = d[mt][nt][3];
        }
    __syncthreads();
    {
        const int r  = tid >> 1;
        const int cb = (tid & 1) * 64;
#pragma unroll
        for (int j = 0; j < 16; j++) {
            int c = cb + j * 4;
            if (n0 + c < N) {  // N, c multiples of 4 -> whole float4 valid
                const float* s = stg + r * LDP + c;
                float v[4] = {s[0], s[1], s[2], s[3]};
#pragma unroll
                for (int q = 0; q < 4; q++) {
                    float val = v[q] + bias[n0 + c + q];
                    if (EPI == EPI_TANH) {
                        val = tanhf(val);
                    } else if (EPI == EPI_DIAG) {
                        float dd = fmaxf(val, 0.f) + dmin[n0 + c + q];
                        val = dd * xin[(size_t)(m0 + r) * NDIM + n0 + c + q];
                    }
                    v[q] = val;
                }
                *reinterpret_cast<float4*>(C + (size_t)(m0 + r) * ldc + n0 + c) =
                    make_float4(v[0], v[1], v[2], v[3]);
            }
        }
    }
}

// ---------------------------------------------------------------------------
// Final: out = L (L^T x) per batch row; L from (off, diag).
// ---------------------------------------------------------------------------
__global__ void __launch_bounds__(256)
final_kernel(const float* __restrict__ off, const float* __restrict__ diag,
             const float* __restrict__ x, float* __restrict__ out) {
    __shared__ float soff[4][OFFDIM];
    __shared__ float sx[4][NDIM];
    __shared__ float sd[4][NDIM];
    __shared__ float sv[4][NDIM];

    const int r    = threadIdx.x >> 6;
    const int lane = threadIdx.x & 63;
    const size_t row = (size_t)blockIdx.x * 4 + r;

    sx[r][lane] = x[row * NDIM + lane];
    sd[r][lane] = diag[row * NDIM + lane];
    const float* offr = off + row * OFFDIM;
    for (int i = lane; i < OFFDIM; i += 64) soff[r][i] = offr[i];
    __syncthreads();

    float v = sd[r][lane] * sx[r][lane];
    for (int i = lane + 1; i < NDIM; i++)
        v += soff[r][i * (i - 1) / 2 + lane] * sx[r][i];
    sv[r][lane] = v;
    __syncthreads();

    float o = sd[r][lane] * v;
    const int base = lane * (lane - 1) / 2;
    for (int j = 0; j < lane; j++) o += soff[r][base + j] * sv[r][j];
    out[row * NDIM + lane] = o;
}

// ---------------------------------------------------------------------------
// Launch. Inputs: x, Wd1, bd1, Wd2, bd2, Wdo, bdo, Wo1, bo1, Wo2, bo2,
//                 Woo, boo, damp_min
// Launch order puts the Woo GEMM 6th so ncu (-s 5 -c 1) profiles it.
// ---------------------------------------------------------------------------
extern "C" void kernel_launch(void* const* d_in, const int* in_sizes, int n_in,
                              void* d_out, int out_size) {
    const float* x    = (const float*)d_in[0];
    const float* Wd1  = (const float*)d_in[1];
    const float* bd1  = (const float*)d_in[2];
    const float* Wd2  = (const float*)d_in[3];
    const float* bd2  = (const float*)d_in[4];
    const float* Wdo  = (const float*)d_in[5];
    const float* bdo  = (const float*)d_in[6];
    const float* Wo1  = (const float*)d_in[7];
    const float* bo1  = (const float*)d_in[8];
    const float* Wo2  = (const float*)d_in[9];
    const float* bo2  = (const float*)d_in[10];
    const float* Woo  = (const float*)d_in[11];
    const float* boo  = (const float*)d_in[12];
    const float* dmin = (const float*)d_in[13];
    float* out = (float*)d_out;

    float *h1, *h2, *h3, *dg, *off;
    uint32_t *wth, *wtl;
    cudaGetSymbolAddress((void**)&h1,  g_h1);
    cudaGetSymbolAddress((void**)&h2,  g_h2);
    cudaGetSymbolAddress((void**)&h3,  g_h3);
    cudaGetSymbolAddress((void**)&dg,  g_diag);
    cudaGetSymbolAddress((void**)&off, g_off);
    cudaGetSymbolAddress((void**)&wth, g_wth);
    cudaGetSymbolAddress((void**)&wtl, g_wtl);

    cudaFuncSetAttribute(gemm_mma<EPI_TANH>,
                         cudaFuncAttributeMaxDynamicSharedMemorySize, GEMM_SMEM);
    cudaFuncSetAttribute(gemm_mma<EPI_BIAS>,
                         cudaFuncAttributeMaxDynamicSharedMemorySize, GEMM_SMEM);
    cudaFuncSetAttribute(gemm_mma<EPI_DIAG>,
                         cudaFuncAttributeMaxDynamicSharedMemorySize, GEMM_SMEM);

    // 1: weight prep (transpose + tf32 split), single launch
    prep_all<<<(WT_TOT + 255) / 256, 256>>>(Wd1, Wd2, Wdo, Wo1, Wo2, Woo, wth, wtl);

    const int MB = B_ROWS / 128;  // 256 m-tiles
    // 2-3: diag hidden layers
    gemm_mma<EPI_TANH><<<dim3(2, MB), 256, GEMM_SMEM>>>(
        x, wth + WT_D1, wtl + WT_D1, bd1, h1, NDIM, HDIM, HDIM, nullptr, nullptr);
    gemm_mma<EPI_TANH><<<dim3(2, MB), 256, GEMM_SMEM>>>(
        h1, wth + WT_D2, wtl + WT_D2, bd2, h2, HDIM, HDIM, HDIM, nullptr, nullptr);
    // 4-5: off hidden layers (h1 free after launch 3; h2 kept for launch 7)
    gemm_mma<EPI_TANH><<<dim3(2, MB), 256, GEMM_SMEM>>>(
        x, wth + WT_O1, wtl + WT_O1, bo1, h1, NDIM, HDIM, HDIM, nullptr, nullptr);
    gemm_mma<EPI_TANH><<<dim3(2, MB), 256, GEMM_SMEM>>>(
        h1, wth + WT_O2, wtl + WT_O2, bo2, h3, HDIM, HDIM, HDIM, nullptr, nullptr);
    // 6: dominant Woo GEMM (profiled by ncu)
    gemm_mma<EPI_BIAS><<<dim3(16, MB), 256, GEMM_SMEM>>>(
        h3, wth + WT_OO, wtl + WT_OO, boo, off, HDIM, OFFDIM, OFFDIM, nullptr, nullptr);
    // 7: diag output
    gemm_mma<EPI_DIAG><<<dim3(1, MB), 256, GEMM_SMEM>>>(
        h2, wth + WT_DO, wtl + WT_DO, bdo, dg, HDIM, NDIM, NDIM, x, dmin);
    // 8: L (L^T x)
    final_kernel<<<B_ROWS / 4, 256>>>(off, dg, x, out);
}